// round 4
// baseline (speedup 1.0000x reference)
#include <cuda_runtime.h>

#define TD 2048
#define CD 512
#define DD 64
#define BH 32
#define RWS 8192
#define NRW 65536

typedef unsigned long long u64;
typedef unsigned int u32;

// ---------------- scratch ----------------
__device__ float g_W[CD * CD];
__device__ float g_w[RWS * CD];
__device__ float g_q[RWS * CD];   // pre-scaled by inv*0.125*log2e
__device__ float g_k[RWS * CD];
__device__ float g_v[RWS * CD];
__device__ float g_srow[BH * TD];
__device__ float g_scol[BH * TD];
__device__ float g_prow[BH * TD];
__device__ float g_pcol[BH * TD];
__device__ float g_y[RWS * CD];

// ---------------- helpers ----------------
__device__ __forceinline__ void fma2(u64& d, u64 a, u64 b) {
    asm("fma.rn.f32x2 %0, %1, %2, %0;" : "+l"(d) : "l"(a), "l"(b));
}
__device__ __forceinline__ float2 unpk(u64 v) {
    float2 f; asm("mov.b64 {%0, %1}, %2;" : "=f"(f.x), "=f"(f.y) : "l"(v)); return f;
}
__device__ __forceinline__ u32 tf32c(float f) {
    u32 r; asm("cvt.rna.tf32.f32 %0, %1;" : "=r"(r) : "f"(f)); return r;
}
__device__ __forceinline__ float ex2(float x) {
    float y; asm("ex2.approx.f32 %0, %1;" : "=f"(y) : "f"(x)); return y;
}
__device__ __forceinline__ void mma8(float* d, const u32* a, const u32* b) {
    asm("mma.sync.aligned.m16n8k8.row.col.f32.tf32.tf32.f32 "
        "{%0,%1,%2,%3},{%4,%5,%6,%7},{%8,%9},{%0,%1,%2,%3};"
        : "+f"(d[0]), "+f"(d[1]), "+f"(d[2]), "+f"(d[3])
        : "r"(a[0]), "r"(a[1]), "r"(a[2]), "r"(a[3]), "r"(b[0]), "r"(b[1]));
}

// ---------------------------------------------------------------- W = dw + qw
__global__ void k_addw(const float* __restrict__ dw, const float* __restrict__ qw) {
    int i = blockIdx.x * 256 + threadIdx.x;
    g_W[i] = dw[i] + qw[i];
}

// ================================================================ g_w = x @ W^T (FFMA2, exact)
__global__ __launch_bounds__(256, 2) void k_wgemm(const float* __restrict__ x) {
    __shared__ __align__(16) float sm[16 * 264 + 16 * 132];
    const int BO = 16 * 264;
    const int tid = threadIdx.x;
    const int tx = tid & 15, ty = tid >> 4;
    const int i0 = blockIdx.y * 128, j0 = blockIdx.x * 128;
    const float* Ab = x + (size_t)i0 * CD;
    const float* Bb = g_W + (size_t)j0 * CD;
    u64 acc[8][4] = {};
    #pragma unroll 1
    for (int s = 0; s < 32; s++) {
        int k0 = s * 16;
        #pragma unroll
        for (int l = 0; l < 2; l++) {
            int idx = tid + l * 256;
            int rr = idx >> 2, c4 = (idx & 3) * 4;
            float4 va = *(const float4*)(Ab + (size_t)rr * CD + k0 + c4);
            sm[(c4 + 0) * 264 + 2 * rr] = va.x; sm[(c4 + 0) * 264 + 2 * rr + 1] = va.x;
            sm[(c4 + 1) * 264 + 2 * rr] = va.y; sm[(c4 + 1) * 264 + 2 * rr + 1] = va.y;
            sm[(c4 + 2) * 264 + 2 * rr] = va.z; sm[(c4 + 2) * 264 + 2 * rr + 1] = va.z;
            sm[(c4 + 3) * 264 + 2 * rr] = va.w; sm[(c4 + 3) * 264 + 2 * rr + 1] = va.w;
            float4 vb = *(const float4*)(Bb + (size_t)rr * CD + k0 + c4);
            sm[BO + (c4 + 0) * 132 + rr] = vb.x;
            sm[BO + (c4 + 1) * 132 + rr] = vb.y;
            sm[BO + (c4 + 2) * 132 + rr] = vb.z;
            sm[BO + (c4 + 3) * 132 + rr] = vb.w;
        }
        __syncthreads();
        #pragma unroll
        for (int kk = 0; kk < 16; kk++) {
            u64 a[8], b[4]; ulonglong2 t;
            t = *(const ulonglong2*)&sm[kk * 264 + ty * 8];       a[0] = t.x; a[1] = t.y;
            t = *(const ulonglong2*)&sm[kk * 264 + ty * 8 + 4];   a[2] = t.x; a[3] = t.y;
            t = *(const ulonglong2*)&sm[kk * 264 + 128 + ty * 8]; a[4] = t.x; a[5] = t.y;
            t = *(const ulonglong2*)&sm[kk * 264 + 132 + ty * 8]; a[6] = t.x; a[7] = t.y;
            t = *(const ulonglong2*)&sm[BO + kk * 132 + tx * 4];      b[0] = t.x; b[1] = t.y;
            t = *(const ulonglong2*)&sm[BO + kk * 132 + 64 + tx * 4]; b[2] = t.x; b[3] = t.y;
            #pragma unroll
            for (int i = 0; i < 8; i++)
                #pragma unroll
                for (int j = 0; j < 4; j++)
                    fma2(acc[i][j], a[i], b[j]);
        }
        __syncthreads();
    }
    float* Cb = g_w + (size_t)i0 * CD + j0;
    #pragma unroll
    for (int i = 0; i < 8; i++) {
        int row = (i < 4) ? ty * 4 + i : 64 + ty * 4 + (i - 4);
        float2 p0 = unpk(acc[i][0]), p1 = unpk(acc[i][1]), p2 = unpk(acc[i][2]), p3 = unpk(acc[i][3]);
        *(float4*)(Cb + (size_t)row * CD + tx * 4)      = make_float4(p0.x, p0.y, p1.x, p1.y);
        *(float4*)(Cb + (size_t)row * CD + 64 + tx * 4) = make_float4(p2.x, p2.y, p3.x, p3.y);
    }
}

// ------------------------------------------- rmsnorm -> q (with log2e/sqrt(D)), k, v
__global__ void k_norm(const float* __restrict__ g1, const float* __restrict__ g2,
                       const float* __restrict__ g3) {
    int warp = (blockIdx.x * blockDim.x + threadIdx.x) >> 5;
    int lane = threadIdx.x & 31;
    size_t off = (size_t)(warp >> 3) * CD + (warp & 7) * DD;
    float x0 = g_w[off + lane], x1 = g_w[off + lane + 32];
    float ss = x0 * x0 + x1 * x1;
    #pragma unroll
    for (int s = 16; s; s >>= 1) ss += __shfl_xor_sync(0xffffffffu, ss, s);
    float inv = rsqrtf(ss * (1.0f / 64.0f) + 1.1920929e-07f);
    float qs = inv * 0.125f * 1.44269504f;   // fold 1/sqrt(D) and log2(e)
    g_q[off + lane]      = x0 * qs  * g1[lane];
    g_q[off + lane + 32] = x1 * qs  * g1[lane + 32];
    g_k[off + lane]      = x0 * inv * g2[lane];
    g_k[off + lane + 32] = x1 * inv * g2[lane + 32];
    g_v[off + lane]      = x0 * inv * g3[lane];
    g_v[off + lane + 32] = x1 * inv * g3[lane + 32];
}

// ================================================================ pass A: row/col sums of 2^(q@k^T)
// 128x128 tile via tf32 MMA; no E store.
__global__ __launch_bounds__(256, 1) void k_sums() {
    __shared__ __align__(16) float sq[128 * 40];
    __shared__ __align__(16) float sk[128 * 40];
    const int tid = threadIdx.x;
    const int lane = tid & 31, warp = tid >> 5;
    const int wm = warp >> 1, wn = warp & 1;
    const int g = lane >> 2, t = lane & 3;
    const int bh = blockIdx.z;
    const int i0 = blockIdx.y * 128, j0 = blockIdx.x * 128;
    const size_t base = (size_t)(bh >> 3) * TD * CD + (bh & 7) * DD;
    const float* qb = g_q + base + (size_t)i0 * CD;
    const float* kb = g_k + base + (size_t)j0 * CD;
    float d[2][8][4] = {};
    #pragma unroll
    for (int stage = 0; stage < 2; stage++) {
        int k0 = stage * 32;
        #pragma unroll
        for (int l = 0; l < 4; l++) {
            int idx = tid + l * 256;
            int rr = idx >> 3, c4 = (idx & 7) * 4;
            int pbase = (c4 & 24) + ((c4 & 4) ? 1 : 0);
            float4 v = *(const float4*)(qb + (size_t)rr * CD + k0 + c4);
            u32* dq = (u32*)&sq[rr * 40 + pbase];
            dq[0] = tf32c(v.x); dq[2] = tf32c(v.y); dq[4] = tf32c(v.z); dq[6] = tf32c(v.w);
            float4 w = *(const float4*)(kb + (size_t)rr * CD + k0 + c4);
            u32* dk = (u32*)&sk[rr * 40 + pbase];
            dk[0] = tf32c(w.x); dk[2] = tf32c(w.y); dk[4] = tf32c(w.z); dk[6] = tf32c(w.w);
        }
        __syncthreads();
        #pragma unroll
        for (int ks = 0; ks < 4; ks++) {
            u32 a[2][4], b[8][2];
            #pragma unroll
            for (int mt = 0; mt < 2; mt++) {
                float2 lo = *(const float2*)&sq[(wm * 32 + mt * 16 + g) * 40 + ks * 8 + 2 * t];
                float2 hi = *(const float2*)&sq[(wm * 32 + mt * 16 + g + 8) * 40 + ks * 8 + 2 * t];
                a[mt][0] = __float_as_uint(lo.x); a[mt][2] = __float_as_uint(lo.y);
                a[mt][1] = __float_as_uint(hi.x); a[mt][3] = __float_as_uint(hi.y);
            }
            #pragma unroll
            for (int nt = 0; nt < 8; nt++) {
                float2 bb = *(const float2*)&sk[(wn * 64 + nt * 8 + g) * 40 + ks * 8 + 2 * t];
                b[nt][0] = __float_as_uint(bb.x); b[nt][1] = __float_as_uint(bb.y);
            }
            #pragma unroll
            for (int mt = 0; mt < 2; mt++)
                #pragma unroll
                for (int nt = 0; nt < 8; nt++)
                    mma8(d[mt][nt], a[mt], b[nt]);
        }
        __syncthreads();
    }
    float csum0[8], csum1[8];
    #pragma unroll
    for (int nt = 0; nt < 8; nt++) { csum0[nt] = 0.f; csum1[nt] = 0.f; }
    float rsum[2][2];
    #pragma unroll
    for (int mt = 0; mt < 2; mt++) {
        rsum[mt][0] = 0.f; rsum[mt][1] = 0.f;
        #pragma unroll
        for (int nt = 0; nt < 8; nt++) {
            float e0 = ex2(d[mt][nt][0]), e1 = ex2(d[mt][nt][1]);
            float e2 = ex2(d[mt][nt][2]), e3 = ex2(d[mt][nt][3]);
            rsum[mt][0] += e0 + e1; rsum[mt][1] += e2 + e3;
            csum0[nt] += e0 + e2;  csum1[nt] += e1 + e3;
        }
    }
    #pragma unroll
    for (int mt = 0; mt < 2; mt++)
        #pragma unroll
        for (int h = 0; h < 2; h++) {
            rsum[mt][h] += __shfl_xor_sync(0xffffffffu, rsum[mt][h], 1);
            rsum[mt][h] += __shfl_xor_sync(0xffffffffu, rsum[mt][h], 2);
        }
    #pragma unroll
    for (int nt = 0; nt < 8; nt++) {
        csum0[nt] += __shfl_xor_sync(0xffffffffu, csum0[nt], 4);
        csum0[nt] += __shfl_xor_sync(0xffffffffu, csum0[nt], 8);
        csum0[nt] += __shfl_xor_sync(0xffffffffu, csum0[nt], 16);
        csum1[nt] += __shfl_xor_sync(0xffffffffu, csum1[nt], 4);
        csum1[nt] += __shfl_xor_sync(0xffffffffu, csum1[nt], 8);
        csum1[nt] += __shfl_xor_sync(0xffffffffu, csum1[nt], 16);
    }
    float* srowp = sq;        // [2][128]
    float* scolp = sq + 256;  // [4][128]
    if (t == 0) {
        #pragma unroll
        for (int mt = 0; mt < 2; mt++) {
            srowp[wn * 128 + wm * 32 + mt * 16 + g]     = rsum[mt][0];
            srowp[wn * 128 + wm * 32 + mt * 16 + g + 8] = rsum[mt][1];
        }
    }
    if (g == 0) {
        #pragma unroll
        for (int nt = 0; nt < 8; nt++) {
            scolp[wm * 128 + wn * 64 + nt * 8 + 2 * t]     = csum0[nt];
            scolp[wm * 128 + wn * 64 + nt * 8 + 2 * t + 1] = csum1[nt];
        }
    }
    __syncthreads();
    if (tid < 128) {
        atomicAdd(&g_srow[bh * TD + i0 + tid], srowp[tid] + srowp[128 + tid]);
    } else {
        int c = tid - 128;
        atomicAdd(&g_scol[bh * TD + j0 + c],
                  scolp[c] + scolp[128 + c] + scolp[256 + c] + scolp[384 + c]);
    }
}

// ------------------------------------------- reciprocals of sums
__global__ void k_recip() {
    int i = blockIdx.x * 256 + threadIdx.x;
    g_prow[i] = 1.0f / g_srow[i];
    g_pcol[i] = 1.0f / g_scol[i];
}

// ================================================================ pass B: fused recompute + y = S@V
// Per CTA: 128-row block of one bh. Loop K-chunks of 64: MMA1 att -> exp2 -> scale -> smem (tf32, perm),
// MMA2 y += S@V. q tile resident in smem. No E materialization.
#define SQ_OFF 0
#define SS_OFF (128 * 72)
#define SK_OFF (SS_OFF + 128 * 72)
#define SV_OFF (SK_OFF + 64 * 72)
#define SPC_OFF (SV_OFF + 64 * 72)
#define FUSED_SMEM ((SPC_OFF + 64) * 4)

__global__ __launch_bounds__(256, 1) void k_fused() {
    extern __shared__ __align__(16) float sm[];
    float* sq = sm + SQ_OFF;
    float* sS = sm + SS_OFF;
    float* sk = sm + SK_OFF;
    float* sV = sm + SV_OFF;
    float* spc = sm + SPC_OFF;
    const int tid = threadIdx.x;
    const int lane = tid & 31, warp = tid >> 5;
    const int wm = warp >> 1, wn = warp & 1;
    const int g = lane >> 2, t = lane & 3;
    const int bh = blockIdx.y;
    const int i0 = blockIdx.x * 128;
    const size_t base = (size_t)(bh >> 3) * TD * CD + (bh & 7) * DD;
    const float* qb = g_q + base + (size_t)i0 * CD;
    const float* kb = g_k + base;
    const float* vb = g_v + base;
    const float* pcb = g_pcol + bh * TD;
    // resident q tile: 128x64, perm layout stride 72, tf32
    #pragma unroll
    for (int l = 0; l < 8; l++) {
        int idx = tid + l * 256;
        int rr = idx >> 4, c4 = (idx & 15) * 4;
        int pbase = (c4 & 56) + ((c4 & 4) ? 1 : 0);
        float4 v = *(const float4*)(qb + (size_t)rr * CD + c4);
        u32* dq = (u32*)&sq[rr * 72 + pbase];
        dq[0] = tf32c(v.x); dq[2] = tf32c(v.y); dq[4] = tf32c(v.z); dq[6] = tf32c(v.w);
    }
    // per-thread prow values for this warp's rows
    float prv[4];
    #pragma unroll
    for (int mt = 0; mt < 2; mt++) {
        prv[mt * 2]     = g_prow[bh * TD + i0 + wm * 32 + mt * 16 + g];
        prv[mt * 2 + 1] = g_prow[bh * TD + i0 + wm * 32 + mt * 16 + g + 8];
    }
    const int p0 = ((t & 1) << 2) | (t >> 1);   // perm pos of col 2t -> {0,4,1,5}
    float dy[2][4][4] = {};
    #pragma unroll 1
    for (int kc = 0; kc < 32; kc++) {
        int k0 = kc * 64;
        __syncthreads();   // protect sk/sV/spc from previous MMA2 readers
        #pragma unroll
        for (int l = 0; l < 4; l++) {
            int idx = tid + l * 256;
            int rr = idx >> 4, c4 = (idx & 15) * 4;
            int pbase = (c4 & 56) + ((c4 & 4) ? 1 : 0);
            float4 w = *(const float4*)(kb + (size_t)(k0 + rr) * CD + c4);
            u32* dk = (u32*)&sk[rr * 72 + pbase];
            dk[0] = tf32c(w.x); dk[2] = tf32c(w.y); dk[4] = tf32c(w.z); dk[6] = tf32c(w.w);
            float4 vv = *(const float4*)(vb + (size_t)(k0 + rr) * CD + c4);
            u32* dv = (u32*)&sV[rr * 72 + c4];
            dv[0] = tf32c(vv.x); dv[1] = tf32c(vv.y); dv[2] = tf32c(vv.z); dv[3] = tf32c(vv.w);
        }
        if (tid < 16) *(float4*)&spc[tid * 4] = *(const float4*)(pcb + k0 + tid * 4);
        __syncthreads();
        // MMA1: att tile 128x64
        float d1[2][4][4] = {};
        #pragma unroll
        for (int ks = 0; ks < 8; ks++) {
            u32 a[2][4], b[4][2];
            #pragma unroll
            for (int mt = 0; mt < 2; mt++) {
                float2 lo = *(const float2*)&sq[(wm * 32 + mt * 16 + g) * 72 + ks * 8 + 2 * t];
                float2 hi = *(const float2*)&sq[(wm * 32 + mt * 16 + g + 8) * 72 + ks * 8 + 2 * t];
                a[mt][0] = __float_as_uint(lo.x); a[mt][2] = __float_as_uint(lo.y);
                a[mt][1] = __float_as_uint(hi.x); a[mt][3] = __float_as_uint(hi.y);
            }
            #pragma unroll
            for (int nt = 0; nt < 4; nt++) {
                float2 bb = *(const float2*)&sk[(wn * 32 + nt * 8 + g) * 72 + ks * 8 + 2 * t];
                b[nt][0] = __float_as_uint(bb.x); b[nt][1] = __float_as_uint(bb.y);
            }
            #pragma unroll
            for (int mt = 0; mt < 2; mt++)
                #pragma unroll
                for (int nt = 0; nt < 4; nt++)
                    mma8(d1[mt][nt], a[mt], b[nt]);
        }
        // epilogue: exp2 + (pr+pc) scale, store tf32 S into perm smem
        #pragma unroll
        for (int mt = 0; mt < 2; mt++) {
            int r0 = (wm * 32 + mt * 16 + g) * 72;
            int r1 = r0 + 8 * 72;
            #pragma unroll
            for (int nt = 0; nt < 4; nt++) {
                int cb = wn * 32 + nt * 8;
                float2 pc2 = *(const float2*)&spc[cb + 2 * t];
                float s00 = pc2.x + prv[mt * 2],     s01 = pc2.y + prv[mt * 2];
                float s10 = pc2.x + prv[mt * 2 + 1], s11 = pc2.y + prv[mt * 2 + 1];
                ((u32*)sS)[r0 + cb + p0]     = tf32c(ex2(d1[mt][nt][0]) * s00);
                ((u32*)sS)[r0 + cb + p0 + 2] = tf32c(ex2(d1[mt][nt][1]) * s01);
                ((u32*)sS)[r1 + cb + p0]     = tf32c(ex2(d1[mt][nt][2]) * s10);
                ((u32*)sS)[r1 + cb + p0 + 2] = tf32c(ex2(d1[mt][nt][3]) * s11);
            }
        }
        __syncthreads();
        // MMA2: y += S @ V
        #pragma unroll
        for (int ks = 0; ks < 8; ks++) {
            u32 a[2][4], b[4][2];
            #pragma unroll
            for (int mt = 0; mt < 2; mt++) {
                float2 lo = *(const float2*)&sS[(wm * 32 + mt * 16 + g) * 72 + ks * 8 + 2 * t];
                float2 hi = *(const float2*)&sS[(wm * 32 + mt * 16 + g + 8) * 72 + ks * 8 + 2 * t];
                a[mt][0] = __float_as_uint(lo.x); a[mt][2] = __float_as_uint(lo.y);
                a[mt][1] = __float_as_uint(hi.x); a[mt][3] = __float_as_uint(hi.y);
            }
            #pragma unroll
            for (int nt = 0; nt < 4; nt++) {
                int n = wn * 32 + nt * 8 + g;
                b[nt][0] = __float_as_uint(sV[(ks * 8 + t) * 72 + n]);
                b[nt][1] = __float_as_uint(sV[(ks * 8 + t + 4) * 72 + n]);
            }
            #pragma unroll
            for (int mt = 0; mt < 2; mt++)
                #pragma unroll
                for (int nt = 0; nt < 4; nt++)
                    mma8(dy[mt][nt], a[mt], b[nt]);
        }
    }
    float* yb = g_y + base + (size_t)i0 * CD;
    #pragma unroll
    for (int mt = 0; mt < 2; mt++) {
        int row0 = wm * 32 + mt * 16 + g;
        #pragma unroll
        for (int nt = 0; nt < 4; nt++) {
            int col = wn * 32 + nt * 8 + 2 * t;
            *(float2*)(yb + (size_t)row0 * CD + col)       = make_float2(dy[mt][nt][0], dy[mt][nt][1]);
            *(float2*)(yb + (size_t)(row0 + 8) * CD + col) = make_float2(dy[mt][nt][2], dy[mt][nt][3]);
        }
    }
}

// ================================================================ out = y @ W (NN, FFMA2, exact)
__global__ __launch_bounds__(256, 2) void k_outgemm(float* __restrict__ out) {
    __shared__ __align__(16) float sm[16 * 264 + 16 * 132];
    const int BO = 16 * 264;
    const int tid = threadIdx.x;
    const int tx = tid & 15, ty = tid >> 4;
    const int i0 = blockIdx.y * 128, j0 = blockIdx.x * 128;
    const float* Ab = g_y + (size_t)i0 * CD;
    u64 acc[8][4] = {};
    #pragma unroll 1
    for (int s = 0; s < 32; s++) {
        int k0 = s * 16;
        #pragma unroll
        for (int l = 0; l < 2; l++) {
            int idx = tid + l * 256;
            int rr = idx >> 2, c4 = (idx & 3) * 4;
            float4 va = *(const float4*)(Ab + (size_t)rr * CD + k0 + c4);
            sm[(c4 + 0) * 264 + 2 * rr] = va.x; sm[(c4 + 0) * 264 + 2 * rr + 1] = va.x;
            sm[(c4 + 1) * 264 + 2 * rr] = va.y; sm[(c4 + 1) * 264 + 2 * rr + 1] = va.y;
            sm[(c4 + 2) * 264 + 2 * rr] = va.z; sm[(c4 + 2) * 264 + 2 * rr + 1] = va.z;
            sm[(c4 + 3) * 264 + 2 * rr] = va.w; sm[(c4 + 3) * 264 + 2 * rr + 1] = va.w;
            int kk = idx >> 5, j4 = (idx & 31) * 4;
            *(float4*)&sm[BO + kk * 132 + j4] =
                *(const float4*)(g_W + (size_t)(k0 + kk) * CD + j0 + j4);
        }
        __syncthreads();
        #pragma unroll
        for (int kk = 0; kk < 16; kk++) {
            u64 a[8], b[4]; ulonglong2 t;
            t = *(const ulonglong2*)&sm[kk * 264 + ty * 8];       a[0] = t.x; a[1] = t.y;
            t = *(const ulonglong2*)&sm[kk * 264 + ty * 8 + 4];   a[2] = t.x; a[3] = t.y;
            t = *(const ulonglong2*)&sm[kk * 264 + 128 + ty * 8]; a[4] = t.x; a[5] = t.y;
            t = *(const ulonglong2*)&sm[kk * 264 + 132 + ty * 8]; a[6] = t.x; a[7] = t.y;
            t = *(const ulonglong2*)&sm[BO + kk * 132 + tx * 4];      b[0] = t.x; b[1] = t.y;
            t = *(const ulonglong2*)&sm[BO + kk * 132 + 64 + tx * 4]; b[2] = t.x; b[3] = t.y;
            #pragma unroll
            for (int i = 0; i < 8; i++)
                #pragma unroll
                for (int j = 0; j < 4; j++)
                    fma2(acc[i][j], a[i], b[j]);
        }
        __syncthreads();
    }
    float* Cb = out + (size_t)i0 * CD + j0;
    #pragma unroll
    for (int i = 0; i < 8; i++) {
        int row = (i < 4) ? ty * 4 + i : 64 + ty * 4 + (i - 4);
        float2 p0 = unpk(acc[i][0]), p1 = unpk(acc[i][1]), p2 = unpk(acc[i][2]), p3 = unpk(acc[i][3]);
        *(float4*)(Cb + (size_t)row * CD + tx * 4)      = make_float4(p0.x, p0.y, p1.x, p1.y);
        *(float4*)(Cb + (size_t)row * CD + 64 + tx * 4) = make_float4(p2.x, p2.y, p3.x, p3.y);
    }
}

extern "C" void kernel_launch(void* const* d_in, const int* in_sizes, int n_in,
                              void* d_out, int out_size) {
    (void)in_sizes; (void)n_in; (void)out_size;
    const float* x  = (const float*)d_in[0];
    const float* dw = (const float*)d_in[1];
    const float* qw = (const float*)d_in[2];
    const float* g1 = (const float*)d_in[3];
    const float* g2 = (const float*)d_in[4];
    const float* g3 = (const float*)d_in[5];
    float* out = (float*)d_out;

    static int smem_set = 0;
    if (!smem_set) {
        cudaFuncSetAttribute(k_fused, cudaFuncAttributeMaxDynamicSharedMemorySize, FUSED_SMEM);
        smem_set = 1;
    }

    float *ps, *pc;
    cudaGetSymbolAddress((void**)&ps, g_srow);
    cudaGetSymbolAddress((void**)&pc, g_scol);
    cudaMemsetAsync(ps, 0, BH * TD * sizeof(float));
    cudaMemsetAsync(pc, 0, BH * TD * sizeof(float));

    k_addw<<<(CD * CD) / 256, 256>>>(dw, qw);
    k_wgemm<<<dim3(CD / 128, RWS / 128), 256>>>(x);
    k_norm<<<NRW / 8, 256>>>(g1, g2, g3);
    k_sums<<<dim3(TD / 128, TD / 128, BH), 256>>>();
    k_recip<<<(BH * TD) / 256, 256>>>();
    k_fused<<<dim3(TD / 128, BH), 256, FUSED_SMEM>>>();
    k_outgemm<<<dim3(CD / 128, RWS / 128), 256>>>(out);
}